// round 14
// baseline (speedup 1.0000x reference)
#include <cuda_runtime.h>
#include <cuda_fp16.h>

#define N_NODES 30000
#define E_EDGES 480000
#define NTILES  3750            // E / 128

// ---------------- device scratch (no allocation allowed) ----------------
__device__ float g_e[E_EDGES];
__device__ float g_v[E_EDGES * 20];
__device__ float g_q[N_NODES * 20];
__device__ float g_Z[N_NODES];

#define C_SS 0.17677669529663687f   // 1/(4*sqrt2)  (== C_SU, exploited)
#define C_UU 0.14433756729740643f   // 1/sqrt(48)
#define C_SU 0.17677669529663687f
#define C_US 0.25f                  // 1/(sqrt8*sqrt2)
#define S0   0.022097086912079608f
#define S1   0.036084391824351615f

typedef unsigned long long ull;
typedef unsigned int u32;
typedef unsigned short u16;

// ---------------- SMEM layout (bytes) ----------------
// W2 hi only; W1 hi only; OPS/EM double-buffered per tileslot.
#define OFF_KHI  0               // 288 rows x 144B = 41472
#define OFF_VHI  41472
#define OFF_W1KH 82944           // 2048
#define OFF_W1VH 84992
#define OFF_OPS0 87040           // slot0: 2 bufs x 24576
#define OFF_OPS1 136192          // slot1: 2 bufs x 24576
#define OFF_EM0  185344          // slot0: 2 bufs x 4096
#define OFF_EM1  193536
#define SMEM_BYTES 201728

// ---------------- helpers ----------------
__device__ __forceinline__ u32 smem_u32(const void* p) {
    u32 a; asm("{ .reg .u64 t; cvta.to.shared.u64 t, %1; cvt.u32.u64 %0, t; }" : "=r"(a) : "l"(p));
    return a;
}
__device__ __forceinline__ u32 lds32(u32 a) {
    u32 v; asm volatile("ld.shared.b32 %0, [%1];" : "=r"(v) : "r"(a)); return v;
}
__device__ __forceinline__ float ldsf(u32 a) {
    float v; asm volatile("ld.shared.f32 %0, [%1];" : "=f"(v) : "r"(a)); return v;
}
__device__ __forceinline__ void stsf(u32 a, float v) {
    asm volatile("st.shared.f32 [%0], %1;" :: "r"(a), "f"(v) : "memory");
}
__device__ __forceinline__ void lds128(u32* r, u32 a) {
    asm volatile("ld.shared.v4.b32 {%0,%1,%2,%3}, [%4];"
                 : "=r"(r[0]), "=r"(r[1]), "=r"(r[2]), "=r"(r[3]) : "r"(a));
}
__device__ __forceinline__ void sts128(u32 a, u32 v0, u32 v1, u32 v2, u32 v3) {
    asm volatile("st.shared.v4.b32 [%0], {%1,%2,%3,%4};" :: "r"(a), "r"(v0), "r"(v1), "r"(v2), "r"(v3) : "memory");
}
__device__ __forceinline__ float silu_f(float x) { return x / (1.f + __expf(-x)); }

__device__ __forceinline__ u32 h2pack(float lo, float hi) {
    __half2 h = __floats2half2_rn(lo, hi);
    return *reinterpret_cast<u32*>(&h);
}

__device__ __forceinline__ void mma16816(float c[4], const u32* a, u32 b0, u32 b1) {
    asm("mma.sync.aligned.m16n8k16.row.col.f32.f16.f16.f32 "
        "{%0,%1,%2,%3}, {%4,%5,%6,%7}, {%8,%9}, {%0,%1,%2,%3};"
        : "+f"(c[0]), "+f"(c[1]), "+f"(c[2]), "+f"(c[3])
        : "r"(a[0]), "r"(a[1]), "r"(a[2]), "r"(a[3]), "r"(b0), "r"(b1));
}

#define SHFL(v, L) __shfl_sync(0xffffffffu, (v), (L))

// layer-2 chunk: single-pass hi (Ah*Bh), K=64, permuted v4 B loads
#define MMA_CHUNK(ch, C0, C1) do { \
    const u32 _rb = (u32)(((ch) * 8 + qr) * 144 + 32 * j); \
    u32 _rh[8]; \
    lds128(_rh,     BHI + _rb); lds128(_rh + 4, BHI + _rb + 16); \
    _Pragma("unroll") \
    for (int _kt = 0; _kt < 4; _kt++) { \
        mma16816(C0, ah + _kt * 4,      _rh[2 * _kt], _rh[2 * _kt + 1]); \
        mma16816(C1, ah + 16 + _kt * 4, _rh[2 * _kt], _rh[2 * _kt + 1]); \
    } \
} while (0)

// ---------------------------------------------------------------------------
// Kernel 1: per-node q pre-contraction (+ zero Z and out)
// ---------------------------------------------------------------------------
__global__ void q_kernel(const float* __restrict__ x,
                         const float* __restrict__ Wq0, const float* __restrict__ Wq1,
                         const float* __restrict__ Wd0, const float* __restrict__ Wd1,
                         float* __restrict__ out)
{
    int n = blockIdx.x * blockDim.x + threadIdx.x;
    if (n >= N_NODES) return;
    g_Z[n] = 0.f;
    float* o = out + (size_t)n * 20;
#pragma unroll
    for (int k = 0; k < 20; k++) o[k] = 0.f;

    const float* xr = x + (size_t)n * 40;
    float q0[8];
#pragma unroll
    for (int b = 0; b < 8; b++) {
        float acc = 0.f;
#pragma unroll
        for (int a = 0; a < 16; a++) acc = fmaf(xr[a], __ldg(Wq0 + a * 8 + b), acc);
        q0[b] = acc;
    }
    float q1[12];
#pragma unroll
    for (int b = 0; b < 4; b++)
#pragma unroll
        for (int c = 0; c < 3; c++) {
            float acc = 0.f;
#pragma unroll
            for (int a = 0; a < 8; a++) acc = fmaf(xr[16 + a * 3 + c], __ldg(Wq1 + a * 4 + b), acc);
            q1[b * 3 + c] = acc;
        }
    float* qo = g_q + (size_t)n * 20;
#pragma unroll
    for (int b = 0; b < 8; b++) {
        float acc = 0.f;
#pragma unroll
        for (int a = 0; a < 8; a++) acc = fmaf(q0[a], __ldg(Wd0 + a * 8 + b), acc);
        qo[b] = acc * S0;
    }
#pragma unroll
    for (int b = 0; b < 4; b++)
#pragma unroll
        for (int c = 0; c < 3; c++) {
            float acc = 0.f;
#pragma unroll
            for (int a = 0; a < 4; a++) acc = fmaf(q1[a * 3 + c], __ldg(Wd1 + a * 4 + b), acc);
            qo[8 + b * 3 + c] = acc * S1;
        }
}

// ---------------------------------------------------------------------------
// Kernel 2: edge kernel — 512 threads, 2 tileslots, double-buffered tables,
//           ONE barrier per tile.
// ---------------------------------------------------------------------------
__global__ __launch_bounds__(512, 1)
void edge_kernel(const float* __restrict__ x, const int* __restrict__ ei,
                 const float* __restrict__ eattr, const float* __restrict__ emb,
                 const float* __restrict__ elen,
                 const float* __restrict__ Wk1, const float* __restrict__ Wk2,
                 const float* __restrict__ Wv1, const float* __restrict__ Wv2)
{
    extern __shared__ char smem[];
    const u32 sb = smem_u32(smem);
    const int tid = threadIdx.x;
    const int ts = tid >> 8;             // tileslot 0/1
    const int phase = (tid >> 7) & 1;    // 0 = K, 1 = V
    const int gt = tid & 127;            // edge row within tile
    const int lane = tid & 31;
    const int j = lane & 3;
    const int qr = lane >> 2;
    const int jh = j >> 1;
    const int wbase = (gt >> 5) << 5;
    const int barid = 1 + ts;

    // ---- stage W1 (fp16 hi only, [h-row][k=a], *0.25) ----
    for (int idx = tid; idx < 1024; idx += 512) {
        int a = idx >> 6, h = idx & 63;
        u32 off = (u32)(h * 32 + a * 2);
        *(u16*)(smem + OFF_W1KH + off) = __half_as_ushort(__float2half_rn(Wk1[idx] * 0.25f));
        *(u16*)(smem + OFF_W1VH + off) = __half_as_ushort(__float2half_rn(Wv1[idx] * 0.25f));
    }
    // ---- stage W2 (fp16 hi only, [n-row][k permuted], *0.125) ----
    for (int idx = tid; idx < 64 * 288; idx += 512) {
        int k = idx / 288, n = idx % 288;
        int p = k >> 1;
        int s = (p & 3) * 8 + (p >> 2);
        u32 off = (u32)(n * 144 + s * 4 + (k & 1) * 2);
        *(u16*)(smem + OFF_KHI + off) = __half_as_ushort(__float2half_rn(Wk2[idx] * 0.125f));
        *(u16*)(smem + OFF_VHI + off) = __half_as_ushort(__float2half_rn(Wv2[idx] * 0.125f));
    }
    __syncthreads();

    const u32 BHI = sb + (phase ? OFF_VHI : OFF_KHI);
    const u32 W1H = sb + (phase ? OFF_W1VH : OFF_W1KH);
    const u32 OPSbase = sb + (ts ? OFF_OPS1 : OFF_OPS0);
    const u32 EMBbase = sb + (ts ? OFF_EM1 : OFF_EM0);

    int lanev[4], rowv[4];
#pragma unroll
    for (int rr = 0; rr < 4; rr++) {
        lanev[rr] = (rr >> 1) * 16 + (rr & 1) * 8 + qr;
        rowv[rr] = wbase + lanev[rr];
    }

    int it = 0;
    for (int tile = blockIdx.x * 2 + ts; tile < NTILES; tile += gridDim.x * 2, it ^= 1) {
        const int tbase = tile * 128;
        const int e = tbase + gt;
        const u32 OPS = OPSbase + (u32)(it * 24576);
        const u32 EMB = EMBbase + (u32)(it * 4096);

        const int dst = ei[E_EDGES + e];
        const float4 ea = *(const float4*)(eattr + (size_t)e * 4);
        const float y0 = ea.x, y1a = ea.y, y1b = ea.z, y1c = ea.w;
        float el = 0.f;

        if (phase == 0) {
            // ---- K group builds ops table + EM (fp16 hi) for this tile ----
            el = elen[e];
            const int src = ei[e];
            const float* xr = x + (size_t)src * 40;
            float xs_[16], xu_[24];
#pragma unroll
            for (int a = 0; a < 16; a++) xs_[a] = __ldg(xr + a);
#pragma unroll
            for (int a = 0; a < 24; a++) xu_[a] = __ldg(xr + 16 + a);
#pragma unroll
            for (int a = 0; a < 16; a++)
                stsf(OPS + (u32)((a * 128 + gt) * 4), xs_[a] * C_SU);      // su (ss = su*y0)
#pragma unroll
            for (int a = 0; a < 8; a++)
                stsf(OPS + (u32)(((16 + a) * 128 + gt) * 4),
                     (xu_[a * 3] * y1a + xu_[a * 3 + 1] * y1b + xu_[a * 3 + 2] * y1c) * C_UU);
            const float y0q = y0 * C_US;
#pragma unroll
            for (int a = 0; a < 24; a++)
                stsf(OPS + (u32)(((24 + a) * 128 + gt) * 4), xu_[a] * y0q);

            const float4* ep = (const float4*)(emb + (size_t)e * 16);
            float em_[16];
#pragma unroll
            for (int k = 0; k < 4; k++) {
                float4 t = __ldg(ep + k);
                em_[4 * k] = t.x; em_[4 * k + 1] = t.y; em_[4 * k + 2] = t.z; em_[4 * k + 3] = t.w;
            }
            u32 hw[8];
#pragma unroll
            for (int w = 0; w < 8; w++) hw[w] = h2pack(em_[2 * w], em_[2 * w + 1]);
            const u32 rb = (u32)(gt * 32);
            sts128(EMB + rb,      hw[0], hw[1], hw[2], hw[3]);
            sts128(EMB + rb + 16, hw[4], hw[5], hw[6], hw[7]);
        }
        // single barrier per tile: tables (this buffer) ready; previous
        // iteration on the other buffer already fully consumed before the
        // previous barrier, so no trailing sync is needed.
        asm volatile("bar.sync %0, 256;" :: "r"(barid) : "memory");

        // ---- EM A-frags (hi only) ----
        u32 ehm[2][4];
#pragma unroll
        for (int mt = 0; mt < 2; mt++) {
            const u32 R0 = (u32)((wbase + 16 * mt + qr) * 32);
            ehm[mt][0] = lds32(EMB + R0 + 4 * j);
            ehm[mt][1] = lds32(EMB + R0 + 256 + 4 * j);
            ehm[mt][2] = lds32(EMB + R0 + 16 + 4 * j);
            ehm[mt][3] = lds32(EMB + R0 + 256 + 16 + 4 * j);
        }

        // ---- layer-1 via mma (K=16, single hi pass) ----
        u32 ah[32];
#pragma unroll
        for (int ktp = 0; ktp < 4; ktp++) {
            float cA0[4] = {0,0,0,0}, cA1[4] = {0,0,0,0};
            float cB0[4] = {0,0,0,0}, cB1[4] = {0,0,0,0};
            const u32 rA = (u32)(((2 * ktp) * 8 + qr) * 32 + 4 * j);
            const u32 rB = rA + 256;
            const u32 bh0A = lds32(W1H + rA), bh1A = lds32(W1H + rA + 16);
            const u32 bh0B = lds32(W1H + rB), bh1B = lds32(W1H + rB + 16);
            mma16816(cA0, ehm[0], bh0A, bh1A); mma16816(cA1, ehm[1], bh0A, bh1A);
            mma16816(cB0, ehm[0], bh0B, bh1B); mma16816(cB1, ehm[1], bh0B, bh1B);
            ah[ktp * 4 + 0]      = h2pack(silu_f(cA0[0]), silu_f(cA0[1]));
            ah[ktp * 4 + 1]      = h2pack(silu_f(cA0[2]), silu_f(cA0[3]));
            ah[ktp * 4 + 2]      = h2pack(silu_f(cB0[0]), silu_f(cB0[1]));
            ah[ktp * 4 + 3]      = h2pack(silu_f(cB0[2]), silu_f(cB0[3]));
            ah[16 + ktp * 4 + 0] = h2pack(silu_f(cA1[0]), silu_f(cA1[1]));
            ah[16 + ktp * 4 + 1] = h2pack(silu_f(cA1[2]), silu_f(cA1[3]));
            ah[16 + ktp * 4 + 2] = h2pack(silu_f(cB1[0]), silu_f(cB1[1]));
            ah[16 + ktp * 4 + 3] = h2pack(silu_f(cB1[2]), silu_f(cB1[3]));
        }

        float y0r[4];
#pragma unroll
        for (int rr = 0; rr < 4; rr++) y0r[rr] = SHFL(y0, lanev[rr]);

        // ---- layer-2: 36 n8 chunks, ops via SMEM ----
        float p0[4][2]  = {{0,0},{0,0},{0,0},{0,0}};
        float psu[4][2] = {{0,0},{0,0},{0,0},{0,0}};
        float pus[4][6] = {{0,0,0,0,0,0},{0,0,0,0,0,0},{0,0,0,0,0,0},{0,0,0,0,0,0}};

#pragma unroll
        for (int ch = 0; ch < 16; ch++) {          // ss: op = su_row(ch) * y0
            float A0[4] = {0,0,0,0}, B0[4] = {0,0,0,0};
            MMA_CHUNK(ch, A0, B0);
#pragma unroll
            for (int rr = 0; rr < 4; rr++) {
                float o = ldsf(OPS + (u32)((ch * 128 + rowv[rr]) * 4)) * y0r[rr];
                float c0 = (rr < 2) ? A0[(rr & 1) * 2]     : B0[(rr & 1) * 2];
                float c1 = (rr < 2) ? A0[(rr & 1) * 2 + 1] : B0[(rr & 1) * 2 + 1];
                p0[rr][0] = fmaf(c0, o, p0[rr][0]);
                p0[rr][1] = fmaf(c1, o, p0[rr][1]);
            }
        }
#pragma unroll
        for (int ch = 16; ch < 24; ch++) {         // uu: rows 16..23
            float A0[4] = {0,0,0,0}, B0[4] = {0,0,0,0};
            MMA_CHUNK(ch, A0, B0);
#pragma unroll
            for (int rr = 0; rr < 4; rr++) {
                float o = ldsf(OPS + (u32)((ch * 128 + rowv[rr]) * 4));
                float c0 = (rr < 2) ? A0[(rr & 1) * 2]     : B0[(rr & 1) * 2];
                float c1 = (rr < 2) ? A0[(rr & 1) * 2 + 1] : B0[(rr & 1) * 2 + 1];
                p0[rr][0] = fmaf(c0, o, p0[rr][0]);
                p0[rr][1] = fmaf(c1, o, p0[rr][1]);
            }
        }
#pragma unroll
        for (int ch = 24; ch < 32; ch++) {         // su: su_row(2*(ch-24)+jh), no y0
            float A0[4] = {0,0,0,0}, B0[4] = {0,0,0,0};
            MMA_CHUNK(ch, A0, B0);
            const int arow = 2 * (ch - 24) + jh;
#pragma unroll
            for (int rr = 0; rr < 4; rr++) {
                float o = ldsf(OPS + (u32)((arow * 128 + rowv[rr]) * 4));
                float c0 = (rr < 2) ? A0[(rr & 1) * 2]     : B0[(rr & 1) * 2];
                float c1 = (rr < 2) ? A0[(rr & 1) * 2 + 1] : B0[(rr & 1) * 2 + 1];
                psu[rr][0] = fmaf(c0, o, psu[rr][0]);
                psu[rr][1] = fmaf(c1, o, psu[rr][1]);
            }
        }
#pragma unroll
        for (int ch = 32; ch < 36; ch++) {         // us: rows 24 + 6*(ch-32) + 3*jh + c
            float A0[4] = {0,0,0,0}, B0[4] = {0,0,0,0};
            MMA_CHUNK(ch, A0, B0);
            const int arow = 24 + 6 * (ch - 32) + 3 * jh;
#pragma unroll
            for (int rr = 0; rr < 4; rr++) {
                const u32 ob = OPS + (u32)((arow * 128 + rowv[rr]) * 4);
                float o0 = ldsf(ob);
                float o1 = ldsf(ob + 512);
                float o2 = ldsf(ob + 1024);
                float c0 = (rr < 2) ? A0[(rr & 1) * 2]     : B0[(rr & 1) * 2];
                float c1 = (rr < 2) ? A0[(rr & 1) * 2 + 1] : B0[(rr & 1) * 2 + 1];
                pus[rr][0] = fmaf(c0, o0, pus[rr][0]);
                pus[rr][1] = fmaf(c0, o1, pus[rr][1]);
                pus[rr][2] = fmaf(c0, o2, pus[rr][2]);
                pus[rr][3] = fmaf(c1, o0, pus[rr][3]);
                pus[rr][4] = fmaf(c1, o1, pus[rr][4]);
                pus[rr][5] = fmaf(c1, o2, pus[rr][5]);
            }
        }

        if (phase == 0) {
            // ---- logit finalize ----
#pragma unroll
            for (int rr = 0; rr < 4; rr++) {
                const int L = lanev[rr];
                const int edge = tbase + rowv[rr];
                const int dstr = SHFL(dst, L);
                const float ya = SHFL(y1a, L), yb = SHFL(y1b, L), yc = SHFL(y1c, L);
                const float elr = SHFL(el, L);
                const float* qd = g_q + (size_t)dstr * 20;
                const int b0 = (2 * j) & 3, b1 = (2 * j + 1) & 3;
                const float qa0 = __ldg(qd + 8 + 3 * b0), qa1 = __ldg(qd + 8 + 3 * b0 + 1), qa2 = __ldg(qd + 8 + 3 * b0 + 2);
                const float qb0 = __ldg(qd + 8 + 3 * b1), qb1 = __ldg(qd + 8 + 3 * b1 + 1), qb2 = __ldg(qd + 8 + 3 * b1 + 2);
                float dp = p0[rr][0] * __ldg(qd + 2 * j) + p0[rr][1] * __ldg(qd + 2 * j + 1);
                dp += psu[rr][0] * (ya * qa0 + yb * qa1 + yc * qa2);
                dp += psu[rr][1] * (ya * qb0 + yb * qb1 + yc * qb2);
                dp += pus[rr][0] * qa0 + pus[rr][1] * qa1 + pus[rr][2] * qa2;
                dp += pus[rr][3] * qb0 + pus[rr][4] * qb1 + pus[rr][5] * qb2;
                dp += __shfl_xor_sync(0xffffffffu, dp, 1);
                dp += __shfl_xor_sync(0xffffffffu, dp, 2);
                if (j == 0) {
                    const float t = 10.f * (1.f - elr * (1.f / 3.15f));
                    const float cut = (t > 0.f) ? expf(-1.f / fmaxf(t, 1e-6f)) : 0.f;
                    const float eat = cut * expf(dp);
                    g_e[edge] = eat;
                    atomicAdd(&g_Z[dstr], eat);
                }
            }
        } else {
            // ---- value finalize ----
#pragma unroll
            for (int rr = 0; rr < 4; rr++) {
                const int L = lanev[rr];
                const int edge = tbase + rowv[rr];
                const float ya = SHFL(y1a, L), yb = SHFL(y1b, L), yc = SHFL(y1c, L);
                float* vp = g_v + (size_t)edge * 20;
                vp[2 * j]     = p0[rr][0];
                vp[2 * j + 1] = p0[rr][1];
                const float s0v = psu[rr][0] + __shfl_xor_sync(0xffffffffu, psu[rr][0], 2);
                const float s1v = psu[rr][1] + __shfl_xor_sync(0xffffffffu, psu[rr][1], 2);
                float ux[6];
#pragma unroll
                for (int c = 0; c < 6; c++)
                    ux[c] = pus[rr][c] + __shfl_xor_sync(0xffffffffu, pus[rr][c], 2);
                if (j < 2) {
                    const int b0 = 2 * j, b1 = 2 * j + 1;
                    vp[8 + 3 * b0]     = fmaf(s0v, ya, ux[0]);
                    vp[8 + 3 * b0 + 1] = fmaf(s0v, yb, ux[1]);
                    vp[8 + 3 * b0 + 2] = fmaf(s0v, yc, ux[2]);
                    vp[8 + 3 * b1]     = fmaf(s1v, ya, ux[3]);
                    vp[8 + 3 * b1 + 1] = fmaf(s1v, yb, ux[4]);
                    vp[8 + 3 * b1 + 2] = fmaf(s1v, yc, ux[5]);
                }
            }
        }
    }
}

// ---------------------------------------------------------------------------
// Kernel 3: normalize + scatter (vectorized red.global.add.v4.f32)
// ---------------------------------------------------------------------------
__global__ void scatter_kernel(const int* __restrict__ ei, float* __restrict__ out)
{
    int e = blockIdx.x * blockDim.x + threadIdx.x;
    if (e >= E_EDGES) return;
    int dst = ei[E_EDGES + e];
    float w = sqrtf(fmaxf(g_e[e] / g_Z[dst], 0.f));
    const float4* vp = (const float4*)(g_v + (size_t)e * 20);
    float* op = out + (size_t)dst * 20;
#pragma unroll
    for (int k4 = 0; k4 < 5; k4++) {
        float4 v = __ldg(vp + k4);
        asm volatile("red.global.add.v4.f32 [%0], {%1,%2,%3,%4};"
                     :: "l"(op + k4 * 4),
                        "f"(w * v.x), "f"(w * v.y), "f"(w * v.z), "f"(w * v.w)
                     : "memory");
    }
}

// ---------------------------------------------------------------------------
extern "C" void kernel_launch(void* const* d_in, const int* in_sizes, int n_in,
                              void* d_out, int out_size)
{
    const float* x    = (const float*)d_in[0];
    const int*   ei   = (const int*)d_in[1];
    const float* eatt = (const float*)d_in[2];
    const float* emb  = (const float*)d_in[3];
    const float* elen = (const float*)d_in[4];
    const float* Wq0  = (const float*)d_in[5];
    const float* Wq1  = (const float*)d_in[6];
    const float* Wk1  = (const float*)d_in[7];
    const float* Wk2  = (const float*)d_in[8];
    const float* Wv1  = (const float*)d_in[9];
    const float* Wv2  = (const float*)d_in[10];
    const float* Wd0  = (const float*)d_in[11];
    const float* Wd1  = (const float*)d_in[12];
    float* out = (float*)d_out;

    cudaFuncSetAttribute(edge_kernel, cudaFuncAttributeMaxDynamicSharedMemorySize, SMEM_BYTES);
    int dev = 0, nsm = 148;
    cudaGetDevice(&dev);
    cudaDeviceGetAttribute(&nsm, cudaDevAttrMultiProcessorCount, dev);

    q_kernel<<<(N_NODES + 255) / 256, 256>>>(x, Wq0, Wq1, Wd0, Wd1, out);
    edge_kernel<<<nsm, 512, SMEM_BYTES>>>(x, ei, eatt, emb, elen, Wk1, Wk2, Wv1, Wv2);
    scatter_kernel<<<(E_EDGES + 255) / 256, 256>>>(ei, out);
    (void)in_sizes; (void)n_in; (void)out_size;
}

// round 15
// speedup vs baseline: 1.0971x; 1.0971x over previous
#include <cuda_runtime.h>
#include <cuda_fp16.h>

#define N_NODES 30000
#define E_EDGES 480000
#define NTILES  3750            // E / 128

// ---------------- device scratch (no allocation allowed) ----------------
__device__ float g_e[E_EDGES];
__device__ float g_v[E_EDGES * 20];
__device__ float g_q[N_NODES * 20];
__device__ float g_Z[N_NODES];

#define C_SS 0.17677669529663687f   // 1/(4*sqrt2)  (== C_SU, exploited)
#define C_UU 0.14433756729740643f   // 1/sqrt(48)
#define C_SU 0.17677669529663687f
#define C_US 0.25f                  // 1/(sqrt8*sqrt2)
#define S0   0.022097086912079608f
#define S1   0.036084391824351615f

typedef unsigned long long ull;
typedef unsigned int u32;
typedef unsigned short u16;

// ---------------- SMEM layout (bytes) ----------------
// W2 hi only; W1 hi only; single OPS/EM buffer per tileslot (R13 structure).
#define OFF_KHI  0               // 288 rows x 144B = 41472
#define OFF_VHI  41472
#define OFF_W1KH 82944           // 2048
#define OFF_W1VH 84992
#define OFF_OPS0 87040           // 48 rows x 128 x f32 = 24576
#define OFF_OPS1 111616
#define OFF_EM0  136192          // 128 rows x 32B
#define OFF_EM1  140288
#define SMEM_BYTES 144384

// ---------------- helpers ----------------
__device__ __forceinline__ u32 smem_u32(const void* p) {
    u32 a; asm("{ .reg .u64 t; cvta.to.shared.u64 t, %1; cvt.u32.u64 %0, t; }" : "=r"(a) : "l"(p));
    return a;
}
__device__ __forceinline__ u32 lds32(u32 a) {
    u32 v; asm volatile("ld.shared.b32 %0, [%1];" : "=r"(v) : "r"(a)); return v;
}
__device__ __forceinline__ float ldsf(u32 a) {
    float v; asm volatile("ld.shared.f32 %0, [%1];" : "=f"(v) : "r"(a)); return v;
}
__device__ __forceinline__ void stsf(u32 a, float v) {
    asm volatile("st.shared.f32 [%0], %1;" :: "r"(a), "f"(v) : "memory");
}
__device__ __forceinline__ void lds128(u32* r, u32 a) {
    asm volatile("ld.shared.v4.b32 {%0,%1,%2,%3}, [%4];"
                 : "=r"(r[0]), "=r"(r[1]), "=r"(r[2]), "=r"(r[3]) : "r"(a));
}
__device__ __forceinline__ void sts128(u32 a, u32 v0, u32 v1, u32 v2, u32 v3) {
    asm volatile("st.shared.v4.b32 [%0], {%1,%2,%3,%4};" :: "r"(a), "r"(v0), "r"(v1), "r"(v2), "r"(v3) : "memory");
}
__device__ __forceinline__ float silu_f(float x) { return x / (1.f + __expf(-x)); }

__device__ __forceinline__ u32 h2pack(float lo, float hi) {
    __half2 h = __floats2half2_rn(lo, hi);
    return *reinterpret_cast<u32*>(&h);
}

__device__ __forceinline__ void mma16816(float c[4], const u32* a, u32 b0, u32 b1) {
    asm("mma.sync.aligned.m16n8k16.row.col.f32.f16.f16.f32 "
        "{%0,%1,%2,%3}, {%4,%5,%6,%7}, {%8,%9}, {%0,%1,%2,%3};"
        : "+f"(c[0]), "+f"(c[1]), "+f"(c[2]), "+f"(c[3])
        : "r"(a[0]), "r"(a[1]), "r"(a[2]), "r"(a[3]), "r"(b0), "r"(b1));
}

#define SHFL(v, L) __shfl_sync(0xffffffffu, (v), (L))

// layer-2 chunk: single-pass hi (Ah*Bh), K=64, permuted v4 B loads
#define MMA_CHUNK(ch, C0, C1) do { \
    const u32 _rb = (u32)(((ch) * 8 + qr) * 144 + 32 * j); \
    u32 _rh[8]; \
    lds128(_rh,     BHI + _rb); lds128(_rh + 4, BHI + _rb + 16); \
    _Pragma("unroll") \
    for (int _kt = 0; _kt < 4; _kt++) { \
        mma16816(C0, ah + _kt * 4,      _rh[2 * _kt], _rh[2 * _kt + 1]); \
        mma16816(C1, ah + 16 + _kt * 4, _rh[2 * _kt], _rh[2 * _kt + 1]); \
    } \
} while (0)

// ---------------------------------------------------------------------------
// Kernel 1: per-node q pre-contraction (+ zero Z and out)
// ---------------------------------------------------------------------------
__global__ void q_kernel(const float* __restrict__ x,
                         const float* __restrict__ Wq0, const float* __restrict__ Wq1,
                         const float* __restrict__ Wd0, const float* __restrict__ Wd1,
                         float* __restrict__ out)
{
    int n = blockIdx.x * blockDim.x + threadIdx.x;
    if (n >= N_NODES) return;
    g_Z[n] = 0.f;
    float* o = out + (size_t)n * 20;
#pragma unroll
    for (int k = 0; k < 20; k++) o[k] = 0.f;

    const float* xr = x + (size_t)n * 40;
    float q0[8];
#pragma unroll
    for (int b = 0; b < 8; b++) {
        float acc = 0.f;
#pragma unroll
        for (int a = 0; a < 16; a++) acc = fmaf(xr[a], __ldg(Wq0 + a * 8 + b), acc);
        q0[b] = acc;
    }
    float q1[12];
#pragma unroll
    for (int b = 0; b < 4; b++)
#pragma unroll
        for (int c = 0; c < 3; c++) {
            float acc = 0.f;
#pragma unroll
            for (int a = 0; a < 8; a++) acc = fmaf(xr[16 + a * 3 + c], __ldg(Wq1 + a * 4 + b), acc);
            q1[b * 3 + c] = acc;
        }
    float* qo = g_q + (size_t)n * 20;
#pragma unroll
    for (int b = 0; b < 8; b++) {
        float acc = 0.f;
#pragma unroll
        for (int a = 0; a < 8; a++) acc = fmaf(q0[a], __ldg(Wd0 + a * 8 + b), acc);
        qo[b] = acc * S0;
    }
#pragma unroll
    for (int b = 0; b < 4; b++)
#pragma unroll
        for (int c = 0; c < 3; c++) {
            float acc = 0.f;
#pragma unroll
            for (int a = 0; a < 4; a++) acc = fmaf(q1[a * 3 + c], __ldg(Wd1 + a * 4 + b), acc);
            qo[8 + b * 3 + c] = acc * S1;
        }
}

// ---------------------------------------------------------------------------
// Kernel 2: edge kernel — 512 threads, 2 tileslots, R13 barrier structure,
//           layer-1 AND layer-2 single-pass hi (balanced 304 HMMA/warp).
// ---------------------------------------------------------------------------
__global__ __launch_bounds__(512, 1)
void edge_kernel(const float* __restrict__ x, const int* __restrict__ ei,
                 const float* __restrict__ eattr, const float* __restrict__ emb,
                 const float* __restrict__ elen,
                 const float* __restrict__ Wk1, const float* __restrict__ Wk2,
                 const float* __restrict__ Wv1, const float* __restrict__ Wv2)
{
    extern __shared__ char smem[];
    const u32 sb = smem_u32(smem);
    const int tid = threadIdx.x;
    const int ts = tid >> 8;             // tileslot 0/1
    const int phase = (tid >> 7) & 1;    // 0 = K, 1 = V
    const int gt = tid & 127;            // edge row within tile
    const int lane = tid & 31;
    const int j = lane & 3;
    const int qr = lane >> 2;
    const int jh = j >> 1;
    const int wbase = (gt >> 5) << 5;
    const int barid = 1 + ts;

    // ---- stage W1 (fp16 hi only, [h-row][k=a], *0.25) ----
    for (int idx = tid; idx < 1024; idx += 512) {
        int a = idx >> 6, h = idx & 63;
        u32 off = (u32)(h * 32 + a * 2);
        *(u16*)(smem + OFF_W1KH + off) = __half_as_ushort(__float2half_rn(Wk1[idx] * 0.25f));
        *(u16*)(smem + OFF_W1VH + off) = __half_as_ushort(__float2half_rn(Wv1[idx] * 0.25f));
    }
    // ---- stage W2 (fp16 hi only, [n-row][k permuted], *0.125) ----
    for (int idx = tid; idx < 64 * 288; idx += 512) {
        int k = idx / 288, n = idx % 288;
        int p = k >> 1;
        int s = (p & 3) * 8 + (p >> 2);
        u32 off = (u32)(n * 144 + s * 4 + (k & 1) * 2);
        *(u16*)(smem + OFF_KHI + off) = __half_as_ushort(__float2half_rn(Wk2[idx] * 0.125f));
        *(u16*)(smem + OFF_VHI + off) = __half_as_ushort(__float2half_rn(Wv2[idx] * 0.125f));
    }
    __syncthreads();

    const u32 BHI = sb + (phase ? OFF_VHI : OFF_KHI);
    const u32 W1H = sb + (phase ? OFF_W1VH : OFF_W1KH);
    const u32 OPS = sb + (ts ? OFF_OPS1 : OFF_OPS0);
    const u32 EMB = sb + (ts ? OFF_EM1 : OFF_EM0);

    int lanev[4], rowv[4];
#pragma unroll
    for (int rr = 0; rr < 4; rr++) {
        lanev[rr] = (rr >> 1) * 16 + (rr & 1) * 8 + qr;
        rowv[rr] = wbase + lanev[rr];
    }

    for (int tile = blockIdx.x * 2 + ts; tile < NTILES; tile += gridDim.x * 2) {
        const int tbase = tile * 128;
        const int e = tbase + gt;

        const int dst = ei[E_EDGES + e];
        const float4 ea = *(const float4*)(eattr + (size_t)e * 4);
        const float y0 = ea.x, y1a = ea.y, y1b = ea.z, y1c = ea.w;
        float el = 0.f;

        if (phase == 0) {
            // ---- K group builds ops table + EM (fp16 hi) for this tile ----
            el = elen[e];
            const int src = ei[e];
            const float* xr = x + (size_t)src * 40;
            float xs_[16], xu_[24];
#pragma unroll
            for (int a = 0; a < 16; a++) xs_[a] = __ldg(xr + a);
#pragma unroll
            for (int a = 0; a < 24; a++) xu_[a] = __ldg(xr + 16 + a);
#pragma unroll
            for (int a = 0; a < 16; a++)
                stsf(OPS + (u32)((a * 128 + gt) * 4), xs_[a] * C_SU);      // su (ss = su*y0)
#pragma unroll
            for (int a = 0; a < 8; a++)
                stsf(OPS + (u32)(((16 + a) * 128 + gt) * 4),
                     (xu_[a * 3] * y1a + xu_[a * 3 + 1] * y1b + xu_[a * 3 + 2] * y1c) * C_UU);
            const float y0q = y0 * C_US;
#pragma unroll
            for (int a = 0; a < 24; a++)
                stsf(OPS + (u32)(((24 + a) * 128 + gt) * 4), xu_[a] * y0q);

            const float4* ep = (const float4*)(emb + (size_t)e * 16);
            float em_[16];
#pragma unroll
            for (int k = 0; k < 4; k++) {
                float4 t = __ldg(ep + k);
                em_[4 * k] = t.x; em_[4 * k + 1] = t.y; em_[4 * k + 2] = t.z; em_[4 * k + 3] = t.w;
            }
            u32 hw[8];
#pragma unroll
            for (int w = 0; w < 8; w++) hw[w] = h2pack(em_[2 * w], em_[2 * w + 1]);
            const u32 rb = (u32)(gt * 32);
            sts128(EMB + rb,      hw[0], hw[1], hw[2], hw[3]);
            sts128(EMB + rb + 16, hw[4], hw[5], hw[6], hw[7]);
        }
        asm volatile("bar.sync %0, 256;" :: "r"(barid) : "memory");

        // ---- EM A-frags (hi only) ----
        u32 ehm[2][4];
#pragma unroll
        for (int mt = 0; mt < 2; mt++) {
            const u32 R0 = (u32)((wbase + 16 * mt + qr) * 32);
            ehm[mt][0] = lds32(EMB + R0 + 4 * j);
            ehm[mt][1] = lds32(EMB + R0 + 256 + 4 * j);
            ehm[mt][2] = lds32(EMB + R0 + 16 + 4 * j);
            ehm[mt][3] = lds32(EMB + R0 + 256 + 16 + 4 * j);
        }

        // ---- layer-1 via mma (K=16, single hi pass) ----
        u32 ah[32];
#pragma unroll
        for (int ktp = 0; ktp < 4; ktp++) {
            float cA0[4] = {0,0,0,0}, cA1[4] = {0,0,0,0};
            float cB0[4] = {0,0,0,0}, cB1[4] = {0,0,0,0};
            const u32 rA = (u32)(((2 * ktp) * 8 + qr) * 32 + 4 * j);
            const u32 rB = rA + 256;
            const u32 bh0A = lds32(W1H + rA), bh1A = lds32(W1H + rA + 16);
            const u32 bh0B = lds32(W1H + rB), bh1B = lds32(W1H + rB + 16);
            mma16816(cA0, ehm[0], bh0A, bh1A); mma16816(cA1, ehm[1], bh0A, bh1A);
            mma16816(cB0, ehm[0], bh0B, bh1B); mma16816(cB1, ehm[1], bh0B, bh1B);
            ah[ktp * 4 + 0]      = h2pack(silu_f(cA0[0]), silu_f(cA0[1]));
            ah[ktp * 4 + 1]      = h2pack(silu_f(cA0[2]), silu_f(cA0[3]));
            ah[ktp * 4 + 2]      = h2pack(silu_f(cB0[0]), silu_f(cB0[1]));
            ah[ktp * 4 + 3]      = h2pack(silu_f(cB0[2]), silu_f(cB0[3]));
            ah[16 + ktp * 4 + 0] = h2pack(silu_f(cA1[0]), silu_f(cA1[1]));
            ah[16 + ktp * 4 + 1] = h2pack(silu_f(cA1[2]), silu_f(cA1[3]));
            ah[16 + ktp * 4 + 2] = h2pack(silu_f(cB1[0]), silu_f(cB1[1]));
            ah[16 + ktp * 4 + 3] = h2pack(silu_f(cB1[2]), silu_f(cB1[3]));
        }
        asm volatile("bar.sync %0, 256;" :: "r"(barid) : "memory");   // EM/OPS write window done

        float y0r[4];
#pragma unroll
        for (int rr = 0; rr < 4; rr++) y0r[rr] = SHFL(y0, lanev[rr]);

        // ---- layer-2: 36 n8 chunks, ops via SMEM ----
        float p0[4][2]  = {{0,0},{0,0},{0,0},{0,0}};
        float psu[4][2] = {{0,0},{0,0},{0,0},{0,0}};
        float pus[4][6] = {{0,0,0,0,0,0},{0,0,0,0,0,0},{0,0,0,0,0,0},{0,0,0,0,0,0}};

#pragma unroll
        for (int ch = 0; ch < 16; ch++) {          // ss: op = su_row(ch) * y0
            float A0[4] = {0,0,0,0}, B0[4] = {0,0,0,0};
            MMA_CHUNK(ch, A0, B0);
#pragma unroll
            for (int rr = 0; rr < 4; rr++) {
                float o = ldsf(OPS + (u32)((ch * 128 + rowv[rr]) * 4)) * y0r[rr];
                float c0 = (rr < 2) ? A0[(rr & 1) * 2]     : B0[(rr & 1) * 2];
                float c1 = (rr < 2) ? A0[(rr & 1) * 2 + 1] : B0[(rr & 1) * 2 + 1];
                p0[rr][0] = fmaf(c0, o, p0[rr][0]);
                p0[rr][1] = fmaf(c1, o, p0[rr][1]);
            }
        }
#pragma unroll
        for (int ch = 16; ch < 24; ch++) {         // uu: rows 16..23
            float A0[4] = {0,0,0,0}, B0[4] = {0,0,0,0};
            MMA_CHUNK(ch, A0, B0);
#pragma unroll
            for (int rr = 0; rr < 4; rr++) {
                float o = ldsf(OPS + (u32)((ch * 128 + rowv[rr]) * 4));
                float c0 = (rr < 2) ? A0[(rr & 1) * 2]     : B0[(rr & 1) * 2];
                float c1 = (rr < 2) ? A0[(rr & 1) * 2 + 1] : B0[(rr & 1) * 2 + 1];
                p0[rr][0] = fmaf(c0, o, p0[rr][0]);
                p0[rr][1] = fmaf(c1, o, p0[rr][1]);
            }
        }
#pragma unroll
        for (int ch = 24; ch < 32; ch++) {         // su: su_row(2*(ch-24)+jh), no y0
            float A0[4] = {0,0,0,0}, B0[4] = {0,0,0,0};
            MMA_CHUNK(ch, A0, B0);
            const int arow = 2 * (ch - 24) + jh;
#pragma unroll
            for (int rr = 0; rr < 4; rr++) {
                float o = ldsf(OPS + (u32)((arow * 128 + rowv[rr]) * 4));
                float c0 = (rr < 2) ? A0[(rr & 1) * 2]     : B0[(rr & 1) * 2];
                float c1 = (rr < 2) ? A0[(rr & 1) * 2 + 1] : B0[(rr & 1) * 2 + 1];
                psu[rr][0] = fmaf(c0, o, psu[rr][0]);
                psu[rr][1] = fmaf(c1, o, psu[rr][1]);
            }
        }
#pragma unroll
        for (int ch = 32; ch < 36; ch++) {         // us: rows 24 + 6*(ch-32) + 3*jh + c
            float A0[4] = {0,0,0,0}, B0[4] = {0,0,0,0};
            MMA_CHUNK(ch, A0, B0);
            const int arow = 24 + 6 * (ch - 32) + 3 * jh;
#pragma unroll
            for (int rr = 0; rr < 4; rr++) {
                const u32 ob = OPS + (u32)((arow * 128 + rowv[rr]) * 4);
                float o0 = ldsf(ob);
                float o1 = ldsf(ob + 512);
                float o2 = ldsf(ob + 1024);
                float c0 = (rr < 2) ? A0[(rr & 1) * 2]     : B0[(rr & 1) * 2];
                float c1 = (rr < 2) ? A0[(rr & 1) * 2 + 1] : B0[(rr & 1) * 2 + 1];
                pus[rr][0] = fmaf(c0, o0, pus[rr][0]);
                pus[rr][1] = fmaf(c0, o1, pus[rr][1]);
                pus[rr][2] = fmaf(c0, o2, pus[rr][2]);
                pus[rr][3] = fmaf(c1, o0, pus[rr][3]);
                pus[rr][4] = fmaf(c1, o1, pus[rr][4]);
                pus[rr][5] = fmaf(c1, o2, pus[rr][5]);
            }
        }

        if (phase == 0) {
            // ---- logit finalize ----
#pragma unroll
            for (int rr = 0; rr < 4; rr++) {
                const int L = lanev[rr];
                const int edge = tbase + rowv[rr];
                const int dstr = SHFL(dst, L);
                const float ya = SHFL(y1a, L), yb = SHFL(y1b, L), yc = SHFL(y1c, L);
                const float elr = SHFL(el, L);
                const float* qd = g_q + (size_t)dstr * 20;
                const int b0 = (2 * j) & 3, b1 = (2 * j + 1) & 3;
                const float qa0 = __ldg(qd + 8 + 3 * b0), qa1 = __ldg(qd + 8 + 3 * b0 + 1), qa2 = __ldg(qd + 8 + 3 * b0 + 2);
                const float qb0 = __ldg(qd + 8 + 3 * b1), qb1 = __ldg(qd + 8 + 3 * b1 + 1), qb2 = __ldg(qd + 8 + 3 * b1 + 2);
                float dp = p0[rr][0] * __ldg(qd + 2 * j) + p0[rr][1] * __ldg(qd + 2 * j + 1);
                dp += psu[rr][0] * (ya * qa0 + yb * qa1 + yc * qa2);
                dp += psu[rr][1] * (ya * qb0 + yb * qb1 + yc * qb2);
                dp += pus[rr][0] * qa0 + pus[rr][1] * qa1 + pus[rr][2] * qa2;
                dp += pus[rr][3] * qb0 + pus[rr][4] * qb1 + pus[rr][5] * qb2;
                dp += __shfl_xor_sync(0xffffffffu, dp, 1);
                dp += __shfl_xor_sync(0xffffffffu, dp, 2);
                if (j == 0) {
                    const float t = 10.f * (1.f - elr * (1.f / 3.15f));
                    const float cut = (t > 0.f) ? expf(-1.f / fmaxf(t, 1e-6f)) : 0.f;
                    const float eat = cut * expf(dp);
                    g_e[edge] = eat;
                    atomicAdd(&g_Z[dstr], eat);
                }
            }
        } else {
            // ---- value finalize ----
#pragma unroll
            for (int rr = 0; rr < 4; rr++) {
                const int L = lanev[rr];
                const int edge = tbase + rowv[rr];
                const float ya = SHFL(y1a, L), yb = SHFL(y1b, L), yc = SHFL(y1c, L);
                float* vp = g_v + (size_t)edge * 20;
                vp[2 * j]     = p0[rr][0];
                vp[2 * j + 1] = p0[rr][1];
                const float s0v = psu[rr][0] + __shfl_xor_sync(0xffffffffu, psu[rr][0], 2);
                const float s1v = psu[rr][1] + __shfl_xor_sync(0xffffffffu, psu[rr][1], 2);
                float ux[6];
#pragma unroll
                for (int c = 0; c < 6; c++)
                    ux[c] = pus[rr][c] + __shfl_xor_sync(0xffffffffu, pus[rr][c], 2);
                if (j < 2) {
                    const int b0 = 2 * j, b1 = 2 * j + 1;
                    vp[8 + 3 * b0]     = fmaf(s0v, ya, ux[0]);
                    vp[8 + 3 * b0 + 1] = fmaf(s0v, yb, ux[1]);
                    vp[8 + 3 * b0 + 2] = fmaf(s0v, yc, ux[2]);
                    vp[8 + 3 * b1]     = fmaf(s1v, ya, ux[3]);
                    vp[8 + 3 * b1 + 1] = fmaf(s1v, yb, ux[4]);
                    vp[8 + 3 * b1 + 2] = fmaf(s1v, yc, ux[5]);
                }
            }
        }
    }
}

// ---------------------------------------------------------------------------
// Kernel 3: normalize + scatter (vectorized red.global.add.v4.f32)
// ---------------------------------------------------------------------------
__global__ void scatter_kernel(const int* __restrict__ ei, float* __restrict__ out)
{
    int e = blockIdx.x * blockDim.x + threadIdx.x;
    if (e >= E_EDGES) return;
    int dst = ei[E_EDGES + e];
    float w = sqrtf(fmaxf(g_e[e] / g_Z[dst], 0.f));
    const float4* vp = (const float4*)(g_v + (size_t)e * 20);
    float* op = out + (size_t)dst * 20;
#pragma unroll
    for (int k4 = 0; k4 < 5; k4++) {
        float4 v = __ldg(vp + k4);
        asm volatile("red.global.add.v4.f32 [%0], {%1,%2,%3,%4};"
                     :: "l"(op + k4 * 4),
                        "f"(w * v.x), "f"(w * v.y), "f"(w * v.z), "f"(w * v.w)
                     : "memory");
    }
}

// ---------------------------------------------------------------------------
extern "C" void kernel_launch(void* const* d_in, const int* in_sizes, int n_in,
                              void* d_out, int out_size)
{
    const float* x    = (const float*)d_in[0];
    const int*   ei   = (const int*)d_in[1];
    const float* eatt = (const float*)d_in[2];
    const float* emb  = (const float*)d_in[3];
    const float* elen = (const float*)d_in[4];
    const float* Wq0  = (const float*)d_in[5];
    const float* Wq1  = (const float*)d_in[6];
    const float* Wk1  = (const float*)d_in[7];
    const float* Wk2  = (const float*)d_in[8];
    const float* Wv1  = (const float*)d_in[9];
    const float* Wv2  = (const float*)d_in[10];
    const float* Wd0  = (const float*)d_in[11];
    const float* Wd1  = (const float*)d_in[12];
    float* out = (float*)d_out;

    cudaFuncSetAttribute(edge_kernel, cudaFuncAttributeMaxDynamicSharedMemorySize, SMEM_BYTES);
    int dev = 0, nsm = 148;
    cudaGetDevice(&dev);
    cudaDeviceGetAttribute(&nsm, cudaDevAttrMultiProcessorCount, dev);

    q_kernel<<<(N_NODES + 255) / 256, 256>>>(x, Wq0, Wq1, Wd0, Wd1, out);
    edge_kernel<<<nsm, 512, SMEM_BYTES>>>(x, ei, eatt, emb, elen, Wk1, Wk2, Wv1, Wv2);
    scatter_kernel<<<(E_EDGES + 255) / 256, 256>>>(ei, out);
    (void)in_sizes; (void)n_in; (void)out_size;
}

// round 16
// speedup vs baseline: 1.0973x; 1.0001x over previous
#include <cuda_runtime.h>
#include <cuda_fp16.h>

#define N_NODES 30000
#define E_EDGES 480000
#define NTILES  3750            // E / 128

// ---------------- device scratch (no allocation allowed) ----------------
__device__ float g_e[E_EDGES];
__device__ float g_v[E_EDGES * 20];
__device__ float g_q[N_NODES * 20];
__device__ float g_Z[N_NODES];

#define C_SS 0.17677669529663687f   // 1/(4*sqrt2)  (== C_SU, exploited)
#define C_UU 0.14433756729740643f   // 1/sqrt(48)
#define C_SU 0.17677669529663687f
#define C_US 0.25f                  // 1/(sqrt8*sqrt2)
#define S0   0.022097086912079608f
#define S1   0.036084391824351615f

typedef unsigned long long ull;
typedef unsigned int u32;
typedef unsigned short u16;

// ---------------- SMEM layout (bytes) ----------------
#define OFF_KHI  0               // 288 rows x 144B = 41472
#define OFF_VHI  41472
#define OFF_W1KH 82944           // 2048
#define OFF_W1VH 84992
#define OFF_OPS0 87040           // 48 rows x 128 x f32 = 24576
#define OFF_OPS1 111616
#define OFF_EM0  136192          // 128 rows x 32B
#define OFF_EM1  140288
#define SMEM_BYTES 144384

// ---------------- helpers ----------------
__device__ __forceinline__ u32 smem_u32(const void* p) {
    u32 a; asm("{ .reg .u64 t; cvta.to.shared.u64 t, %1; cvt.u32.u64 %0, t; }" : "=r"(a) : "l"(p));
    return a;
}
__device__ __forceinline__ u32 lds32(u32 a) {
    u32 v; asm volatile("ld.shared.b32 %0, [%1];" : "=r"(v) : "r"(a)); return v;
}
__device__ __forceinline__ float ldsf(u32 a) {
    float v; asm volatile("ld.shared.f32 %0, [%1];" : "=f"(v) : "r"(a)); return v;
}
__device__ __forceinline__ void stsf(u32 a, float v) {
    asm volatile("st.shared.f32 [%0], %1;" :: "r"(a), "f"(v) : "memory");
}
__device__ __forceinline__ void lds128(u32* r, u32 a) {
    asm volatile("ld.shared.v4.b32 {%0,%1,%2,%3}, [%4];"
                 : "=r"(r[0]), "=r"(r[1]), "=r"(r[2]), "=r"(r[3]) : "r"(a));
}
__device__ __forceinline__ void sts128(u32 a, u32 v0, u32 v1, u32 v2, u32 v3) {
    asm volatile("st.shared.v4.b32 [%0], {%1,%2,%3,%4};" :: "r"(a), "r"(v0), "r"(v1), "r"(v2), "r"(v3) : "memory");
}
__device__ __forceinline__ float silu_f(float x) { return x / (1.f + __expf(-x)); }

__device__ __forceinline__ u32 h2pack(float lo, float hi) {
    __half2 h = __floats2half2_rn(lo, hi);
    return *reinterpret_cast<u32*>(&h);
}

__device__ __forceinline__ void mma16816(float c[4], const u32* a, u32 b0, u32 b1) {
    asm("mma.sync.aligned.m16n8k16.row.col.f32.f16.f16.f32 "
        "{%0,%1,%2,%3}, {%4,%5,%6,%7}, {%8,%9}, {%0,%1,%2,%3};"
        : "+f"(c[0]), "+f"(c[1]), "+f"(c[2]), "+f"(c[3])
        : "r"(a[0]), "r"(a[1]), "r"(a[2]), "r"(a[3]), "r"(b0), "r"(b1));
}

#define SHFL(v, L) __shfl_sync(0xffffffffu, (v), (L))

// layer-2 chunk: single-pass hi (Ah*Bh), K=64, permuted v4 B loads
#define MMA_CHUNK(ch, C0, C1) do { \
    const u32 _rb = (u32)(((ch) * 8 + qr) * 144 + 32 * j); \
    u32 _rh[8]; \
    lds128(_rh,     BHI + _rb); lds128(_rh + 4, BHI + _rb + 16); \
    _Pragma("unroll") \
    for (int _kt = 0; _kt < 4; _kt++) { \
        mma16816(C0, ah + _kt * 4,      _rh[2 * _kt], _rh[2 * _kt + 1]); \
        mma16816(C1, ah + 16 + _kt * 4, _rh[2 * _kt], _rh[2 * _kt + 1]); \
    } \
} while (0)

// ---------------------------------------------------------------------------
// Kernel 1: per-node q pre-contraction (+ zero Z and out)
// ---------------------------------------------------------------------------
__global__ void q_kernel(const float* __restrict__ x,
                         const float* __restrict__ Wq0, const float* __restrict__ Wq1,
                         const float* __restrict__ Wd0, const float* __restrict__ Wd1,
                         float* __restrict__ out)
{
    int n = blockIdx.x * blockDim.x + threadIdx.x;
    if (n >= N_NODES) return;
    g_Z[n] = 0.f;
    float* o = out + (size_t)n * 20;
#pragma unroll
    for (int k = 0; k < 20; k++) o[k] = 0.f;

    const float* xr = x + (size_t)n * 40;
    float q0[8];
#pragma unroll
    for (int b = 0; b < 8; b++) {
        float acc = 0.f;
#pragma unroll
        for (int a = 0; a < 16; a++) acc = fmaf(xr[a], __ldg(Wq0 + a * 8 + b), acc);
        q0[b] = acc;
    }
    float q1[12];
#pragma unroll
    for (int b = 0; b < 4; b++)
#pragma unroll
        for (int c = 0; c < 3; c++) {
            float acc = 0.f;
#pragma unroll
            for (int a = 0; a < 8; a++) acc = fmaf(xr[16 + a * 3 + c], __ldg(Wq1 + a * 4 + b), acc);
            q1[b * 3 + c] = acc;
        }
    float* qo = g_q + (size_t)n * 20;
#pragma unroll
    for (int b = 0; b < 8; b++) {
        float acc = 0.f;
#pragma unroll
        for (int a = 0; a < 8; a++) acc = fmaf(q0[a], __ldg(Wd0 + a * 8 + b), acc);
        qo[b] = acc * S0;
    }
#pragma unroll
    for (int b = 0; b < 4; b++)
#pragma unroll
        for (int c = 0; c < 3; c++) {
            float acc = 0.f;
#pragma unroll
            for (int a = 0; a < 4; a++) acc = fmaf(q1[a * 3 + c], __ldg(Wd1 + a * 4 + b), acc);
            qo[8 + b * 3 + c] = acc * S1;
        }
}

// ---------------------------------------------------------------------------
// Kernel 2: edge kernel — 512 threads, 2 tileslots.
//   Staging split: K threads build OPS; V threads build EM. bar#2 placed
//   AFTER layer-2 OPS reads (race-free, R13-proven position).
// ---------------------------------------------------------------------------
__global__ __launch_bounds__(512, 1)
void edge_kernel(const float* __restrict__ x, const int* __restrict__ ei,
                 const float* __restrict__ eattr, const float* __restrict__ emb,
                 const float* __restrict__ elen,
                 const float* __restrict__ Wk1, const float* __restrict__ Wk2,
                 const float* __restrict__ Wv1, const float* __restrict__ Wv2)
{
    extern __shared__ char smem[];
    const u32 sb = smem_u32(smem);
    const int tid = threadIdx.x;
    const int ts = tid >> 8;             // tileslot 0/1
    const int phase = (tid >> 7) & 1;    // 0 = K, 1 = V
    const int gt = tid & 127;            // edge row within tile
    const int lane = tid & 31;
    const int j = lane & 3;
    const int qr = lane >> 2;
    const int jh = j >> 1;
    const int wbase = (gt >> 5) << 5;
    const int barid = 1 + ts;

    // ---- stage W1 (fp16 hi only, [h-row][k=a], *0.25) ----
    for (int idx = tid; idx < 1024; idx += 512) {
        int a = idx >> 6, h = idx & 63;
        u32 off = (u32)(h * 32 + a * 2);
        *(u16*)(smem + OFF_W1KH + off) = __half_as_ushort(__float2half_rn(Wk1[idx] * 0.25f));
        *(u16*)(smem + OFF_W1VH + off) = __half_as_ushort(__float2half_rn(Wv1[idx] * 0.25f));
    }
    // ---- stage W2 (fp16 hi only, [n-row][k permuted], *0.125) ----
    for (int idx = tid; idx < 64 * 288; idx += 512) {
        int k = idx / 288, n = idx % 288;
        int p = k >> 1;
        int s = (p & 3) * 8 + (p >> 2);
        u32 off = (u32)(n * 144 + s * 4 + (k & 1) * 2);
        *(u16*)(smem + OFF_KHI + off) = __half_as_ushort(__float2half_rn(Wk2[idx] * 0.125f));
        *(u16*)(smem + OFF_VHI + off) = __half_as_ushort(__float2half_rn(Wv2[idx] * 0.125f));
    }
    __syncthreads();

    const u32 BHI = sb + (phase ? OFF_VHI : OFF_KHI);
    const u32 W1H = sb + (phase ? OFF_W1VH : OFF_W1KH);
    const u32 OPS = sb + (ts ? OFF_OPS1 : OFF_OPS0);
    const u32 EMB = sb + (ts ? OFF_EM1 : OFF_EM0);

    int lanev[4], rowv[4];
#pragma unroll
    for (int rr = 0; rr < 4; rr++) {
        lanev[rr] = (rr >> 1) * 16 + (rr & 1) * 8 + qr;
        rowv[rr] = wbase + lanev[rr];
    }

    for (int tile = blockIdx.x * 2 + ts; tile < NTILES; tile += gridDim.x * 2) {
        const int tbase = tile * 128;
        const int e = tbase + gt;

        const int dst = ei[E_EDGES + e];
        const float4 ea = *(const float4*)(eattr + (size_t)e * 4);
        const float y0 = ea.x, y1a = ea.y, y1b = ea.z, y1c = ea.w;
        float el = 0.f;

        if (phase == 0) {
            // ---- K group: ops table (x gather) ----
            el = elen[e];
            const int src = ei[e];
            const float* xr = x + (size_t)src * 40;
            float xs_[16], xu_[24];
#pragma unroll
            for (int a = 0; a < 16; a++) xs_[a] = __ldg(xr + a);
#pragma unroll
            for (int a = 0; a < 24; a++) xu_[a] = __ldg(xr + 16 + a);
#pragma unroll
            for (int a = 0; a < 16; a++)
                stsf(OPS + (u32)((a * 128 + gt) * 4), xs_[a] * C_SU);      // su (ss = su*y0)
#pragma unroll
            for (int a = 0; a < 8; a++)
                stsf(OPS + (u32)(((16 + a) * 128 + gt) * 4),
                     (xu_[a * 3] * y1a + xu_[a * 3 + 1] * y1b + xu_[a * 3 + 2] * y1c) * C_UU);
            const float y0q = y0 * C_US;
#pragma unroll
            for (int a = 0; a < 24; a++)
                stsf(OPS + (u32)(((24 + a) * 128 + gt) * 4), xu_[a] * y0q);
        } else {
            // ---- V group: EM table (emb load + fp16 pack) ----
            const float4* ep = (const float4*)(emb + (size_t)e * 16);
            float em_[16];
#pragma unroll
            for (int k = 0; k < 4; k++) {
                float4 t = __ldg(ep + k);
                em_[4 * k] = t.x; em_[4 * k + 1] = t.y; em_[4 * k + 2] = t.z; em_[4 * k + 3] = t.w;
            }
            u32 hw[8];
#pragma unroll
            for (int w = 0; w < 8; w++) hw[w] = h2pack(em_[2 * w], em_[2 * w + 1]);
            const u32 rb = (u32)(gt * 32);
            sts128(EMB + rb,      hw[0], hw[1], hw[2], hw[3]);
            sts128(EMB + rb + 16, hw[4], hw[5], hw[6], hw[7]);
        }
        asm volatile("bar.sync %0, 256;" :: "r"(barid) : "memory");

        // ---- EM A-frags (hi only) ----
        u32 ehm[2][4];
#pragma unroll
        for (int mt = 0; mt < 2; mt++) {
            const u32 R0 = (u32)((wbase + 16 * mt + qr) * 32);
            ehm[mt][0] = lds32(EMB + R0 + 4 * j);
            ehm[mt][1] = lds32(EMB + R0 + 256 + 4 * j);
            ehm[mt][2] = lds32(EMB + R0 + 16 + 4 * j);
            ehm[mt][3] = lds32(EMB + R0 + 256 + 16 + 4 * j);
        }

        // ---- layer-1 via mma (K=16, single hi pass) ----
        u32 ah[32];
#pragma unroll
        for (int ktp = 0; ktp < 4; ktp++) {
            float cA0[4] = {0,0,0,0}, cA1[4] = {0,0,0,0};
            float cB0[4] = {0,0,0,0}, cB1[4] = {0,0,0,0};
            const u32 rA = (u32)(((2 * ktp) * 8 + qr) * 32 + 4 * j);
            const u32 rB = rA + 256;
            const u32 bh0A = lds32(W1H + rA), bh1A = lds32(W1H + rA + 16);
            const u32 bh0B = lds32(W1H + rB), bh1B = lds32(W1H + rB + 16);
            mma16816(cA0, ehm[0], bh0A, bh1A); mma16816(cA1, ehm[1], bh0A, bh1A);
            mma16816(cB0, ehm[0], bh0B, bh1B); mma16816(cB1, ehm[1], bh0B, bh1B);
            ah[ktp * 4 + 0]      = h2pack(silu_f(cA0[0]), silu_f(cA0[1]));
            ah[ktp * 4 + 1]      = h2pack(silu_f(cA0[2]), silu_f(cA0[3]));
            ah[ktp * 4 + 2]      = h2pack(silu_f(cB0[0]), silu_f(cB0[1]));
            ah[ktp * 4 + 3]      = h2pack(silu_f(cB0[2]), silu_f(cB0[3]));
            ah[16 + ktp * 4 + 0] = h2pack(silu_f(cA1[0]), silu_f(cA1[1]));
            ah[16 + ktp * 4 + 1] = h2pack(silu_f(cA1[2]), silu_f(cA1[3]));
            ah[16 + ktp * 4 + 2] = h2pack(silu_f(cB1[0]), silu_f(cB1[1]));
            ah[16 + ktp * 4 + 3] = h2pack(silu_f(cB1[2]), silu_f(cB1[3]));
        }

        float y0r[4];
#pragma unroll
        for (int rr = 0; rr < 4; rr++) y0r[rr] = SHFL(y0, lanev[rr]);

        // ---- layer-2: 36 n8 chunks, ops via SMEM ----
        float p0[4][2]  = {{0,0},{0,0},{0,0},{0,0}};
        float psu[4][2] = {{0,0},{0,0},{0,0},{0,0}};
        float pus[4][6] = {{0,0,0,0,0,0},{0,0,0,0,0,0},{0,0,0,0,0,0},{0,0,0,0,0,0}};

#pragma unroll
        for (int ch = 0; ch < 16; ch++) {          // ss: op = su_row(ch) * y0
            float A0[4] = {0,0,0,0}, B0[4] = {0,0,0,0};
            MMA_CHUNK(ch, A0, B0);
#pragma unroll
            for (int rr = 0; rr < 4; rr++) {
                float o = ldsf(OPS + (u32)((ch * 128 + rowv[rr]) * 4)) * y0r[rr];
                float c0 = (rr < 2) ? A0[(rr & 1) * 2]     : B0[(rr & 1) * 2];
                float c1 = (rr < 2) ? A0[(rr & 1) * 2 + 1] : B0[(rr & 1) * 2 + 1];
                p0[rr][0] = fmaf(c0, o, p0[rr][0]);
                p0[rr][1] = fmaf(c1, o, p0[rr][1]);
            }
        }
#pragma unroll
        for (int ch = 16; ch < 24; ch++) {         // uu: rows 16..23
            float A0[4] = {0,0,0,0}, B0[4] = {0,0,0,0};
            MMA_CHUNK(ch, A0, B0);
#pragma unroll
            for (int rr = 0; rr < 4; rr++) {
                float o = ldsf(OPS + (u32)((ch * 128 + rowv[rr]) * 4));
                float c0 = (rr < 2) ? A0[(rr & 1) * 2]     : B0[(rr & 1) * 2];
                float c1 = (rr < 2) ? A0[(rr & 1) * 2 + 1] : B0[(rr & 1) * 2 + 1];
                p0[rr][0] = fmaf(c0, o, p0[rr][0]);
                p0[rr][1] = fmaf(c1, o, p0[rr][1]);
            }
        }
#pragma unroll
        for (int ch = 24; ch < 32; ch++) {         // su: su_row(2*(ch-24)+jh), no y0
            float A0[4] = {0,0,0,0}, B0[4] = {0,0,0,0};
            MMA_CHUNK(ch, A0, B0);
            const int arow = 2 * (ch - 24) + jh;
#pragma unroll
            for (int rr = 0; rr < 4; rr++) {
                float o = ldsf(OPS + (u32)((arow * 128 + rowv[rr]) * 4));
                float c0 = (rr < 2) ? A0[(rr & 1) * 2]     : B0[(rr & 1) * 2];
                float c1 = (rr < 2) ? A0[(rr & 1) * 2 + 1] : B0[(rr & 1) * 2 + 1];
                psu[rr][0] = fmaf(c0, o, psu[rr][0]);
                psu[rr][1] = fmaf(c1, o, psu[rr][1]);
            }
        }
#pragma unroll
        for (int ch = 32; ch < 36; ch++) {         // us: rows 24 + 6*(ch-32) + 3*jh + c
            float A0[4] = {0,0,0,0}, B0[4] = {0,0,0,0};
            MMA_CHUNK(ch, A0, B0);
            const int arow = 24 + 6 * (ch - 32) + 3 * jh;
#pragma unroll
            for (int rr = 0; rr < 4; rr++) {
                const u32 ob = OPS + (u32)((arow * 128 + rowv[rr]) * 4);
                float o0 = ldsf(ob);
                float o1 = ldsf(ob + 512);
                float o2 = ldsf(ob + 1024);
                float c0 = (rr < 2) ? A0[(rr & 1) * 2]     : B0[(rr & 1) * 2];
                float c1 = (rr < 2) ? A0[(rr & 1) * 2 + 1] : B0[(rr & 1) * 2 + 1];
                pus[rr][0] = fmaf(c0, o0, pus[rr][0]);
                pus[rr][1] = fmaf(c0, o1, pus[rr][1]);
                pus[rr][2] = fmaf(c0, o2, pus[rr][2]);
                pus[rr][3] = fmaf(c1, o0, pus[rr][3]);
                pus[rr][4] = fmaf(c1, o1, pus[rr][4]);
                pus[rr][5] = fmaf(c1, o2, pus[rr][5]);
            }
        }

        // all OPS/EM reads for this tile done -> next tile's writers may proceed
        asm volatile("bar.sync %0, 256;" :: "r"(barid) : "memory");

        if (phase == 0) {
            // ---- logit finalize ----
#pragma unroll
            for (int rr = 0; rr < 4; rr++) {
                const int L = lanev[rr];
                const int edge = tbase + rowv[rr];
                const int dstr = SHFL(dst, L);
                const float ya = SHFL(y1a, L), yb = SHFL(y1b, L), yc = SHFL(y1c, L);
                const float elr = SHFL(el, L);
                const float* qd = g_q + (size_t)dstr * 20;
                const int b0 = (2 * j) & 3, b1 = (2 * j + 1) & 3;
                const float qa0 = __ldg(qd + 8 + 3 * b0), qa1 = __ldg(qd + 8 + 3 * b0 + 1), qa2 = __ldg(qd + 8 + 3 * b0 + 2);
                const float qb0 = __ldg(qd + 8 + 3 * b1), qb1 = __ldg(qd + 8 + 3 * b1 + 1), qb2 = __ldg(qd + 8 + 3 * b1 + 2);
                float dp = p0[rr][0] * __ldg(qd + 2 * j) + p0[rr][1] * __ldg(qd + 2 * j + 1);
                dp += psu[rr][0] * (ya * qa0 + yb * qa1 + yc * qa2);
                dp += psu[rr][1] * (ya * qb0 + yb * qb1 + yc * qb2);
                dp += pus[rr][0] * qa0 + pus[rr][1] * qa1 + pus[rr][2] * qa2;
                dp += pus[rr][3] * qb0 + pus[rr][4] * qb1 + pus[rr][5] * qb2;
                dp += __shfl_xor_sync(0xffffffffu, dp, 1);
                dp += __shfl_xor_sync(0xffffffffu, dp, 2);
                if (j == 0) {
                    const float t = 10.f * (1.f - elr * (1.f / 3.15f));
                    const float cut = (t > 0.f) ? expf(-1.f / fmaxf(t, 1e-6f)) : 0.f;
                    const float eat = cut * expf(dp);
                    g_e[edge] = eat;
                    atomicAdd(&g_Z[dstr], eat);
                }
            }
        } else {
            // ---- value finalize ----
#pragma unroll
            for (int rr = 0; rr < 4; rr++) {
                const int L = lanev[rr];
                const int edge = tbase + rowv[rr];
                const float ya = SHFL(y1a, L), yb = SHFL(y1b, L), yc = SHFL(y1c, L);
                float* vp = g_v + (size_t)edge * 20;
                vp[2 * j]     = p0[rr][0];
                vp[2 * j + 1] = p0[rr][1];
                const float s0v = psu[rr][0] + __shfl_xor_sync(0xffffffffu, psu[rr][0], 2);
                const float s1v = psu[rr][1] + __shfl_xor_sync(0xffffffffu, psu[rr][1], 2);
                float ux[6];
#pragma unroll
                for (int c = 0; c < 6; c++)
                    ux[c] = pus[rr][c] + __shfl_xor_sync(0xffffffffu, pus[rr][c], 2);
                if (j < 2) {
                    const int b0 = 2 * j, b1 = 2 * j + 1;
                    vp[8 + 3 * b0]     = fmaf(s0v, ya, ux[0]);
                    vp[8 + 3 * b0 + 1] = fmaf(s0v, yb, ux[1]);
                    vp[8 + 3 * b0 + 2] = fmaf(s0v, yc, ux[2]);
                    vp[8 + 3 * b1]     = fmaf(s1v, ya, ux[3]);
                    vp[8 + 3 * b1 + 1] = fmaf(s1v, yb, ux[4]);
                    vp[8 + 3 * b1 + 2] = fmaf(s1v, yc, ux[5]);
                }
            }
        }
    }
}

// ---------------------------------------------------------------------------
// Kernel 3: normalize + scatter (vectorized red.global.add.v4.f32)
// ---------------------------------------------------------------------------
__global__ void scatter_kernel(const int* __restrict__ ei, float* __restrict__ out)
{
    int e = blockIdx.x * blockDim.x + threadIdx.x;
    if (e >= E_EDGES) return;
    int dst = ei[E_EDGES + e];
    float w = sqrtf(fmaxf(g_e[e] / g_Z[dst], 0.f));
    const float4* vp = (const float4*)(g_v + (size_t)e * 20);
    float* op = out + (size_t)dst * 20;
#pragma unroll
    for (int k4 = 0; k4 < 5; k4++) {
        float4 v = __ldg(vp + k4);
        asm volatile("red.global.add.v4.f32 [%0], {%1,%2,%3,%4};"
                     :: "l"(op + k4 * 4),
                        "f"(w * v.x), "f"(w * v.y), "f"(w * v.z), "f"(w * v.w)
                     : "memory");
    }
}

// ---------------------------------------------------------------------------
extern "C" void kernel_launch(void* const* d_in, const int* in_sizes, int n_in,
                              void* d_out, int out_size)
{
    const float* x    = (const float*)d_in[0];
    const int*   ei   = (const int*)d_in[1];
    const float* eatt = (const float*)d_in[2];
    const float* emb  = (const float*)d_in[3];
    const float* elen = (const float*)d_in[4];
    const float* Wq0  = (const float*)d_in[5];
    const float* Wq1  = (const float*)d_in[6];
    const float* Wk1  = (const float*)d_in[7];
    const float* Wk2  = (const float*)d_in[8];
    const float* Wv1  = (const float*)d_in[9];
    const float* Wv2  = (const float*)d_in[10];
    const float* Wd0  = (const float*)d_in[11];
    const float* Wd1  = (const float*)d_in[12];
    float* out = (float*)d_out;

    cudaFuncSetAttribute(edge_kernel, cudaFuncAttributeMaxDynamicSharedMemorySize, SMEM_BYTES);
    int dev = 0, nsm = 148;
    cudaGetDevice(&dev);
    cudaDeviceGetAttribute(&nsm, cudaDevAttrMultiProcessorCount, dev);

    q_kernel<<<(N_NODES + 255) / 256, 256>>>(x, Wq0, Wq1, Wd0, Wd1, out);
    edge_kernel<<<nsm, 512, SMEM_BYTES>>>(x, ei, eatt, emb, elen, Wk1, Wk2, Wv1, Wv2);
    scatter_kernel<<<(E_EDGES + 255) / 256, 256>>>(ei, out);
    (void)in_sizes; (void)n_in; (void)out_size;
}

// round 17
// speedup vs baseline: 1.0990x; 1.0016x over previous
#include <cuda_runtime.h>
#include <cuda_fp16.h>

#define N_NODES 30000
#define E_EDGES 480000
#define NTILES  3750            // E / 128

// ---------------- device scratch (no allocation allowed) ----------------
__device__ float g_e[E_EDGES];
__device__ float g_v[E_EDGES * 20];
__device__ float g_q[N_NODES * 20];
__device__ float g_Z[N_NODES];
__device__ unsigned int g_tile_ctr;

#define C_SS 0.17677669529663687f   // 1/(4*sqrt2)  (== C_SU, exploited)
#define C_UU 0.14433756729740643f   // 1/sqrt(48)
#define C_SU 0.17677669529663687f
#define C_US 0.25f                  // 1/(sqrt8*sqrt2)
#define S0   0.022097086912079608f
#define S1   0.036084391824351615f

typedef unsigned long long ull;
typedef unsigned int u32;
typedef unsigned short u16;

// ---------------- SMEM layout (bytes) ----------------
#define OFF_KHI  0               // 288 rows x 144B = 41472
#define OFF_VHI  41472
#define OFF_W1KH 82944           // 2048
#define OFF_W1VH 84992
#define OFF_OPS0 87040           // 48 rows x 128 x f32 = 24576
#define OFF_OPS1 111616
#define OFF_EM0  136192          // 128 rows x 32B
#define OFF_EM1  140288
#define OFF_NEXT 144384          // 2 x int (next-tile mailbox per slot)
#define SMEM_BYTES 144400

// ---------------- helpers ----------------
__device__ __forceinline__ u32 smem_u32(const void* p) {
    u32 a; asm("{ .reg .u64 t; cvta.to.shared.u64 t, %1; cvt.u32.u64 %0, t; }" : "=r"(a) : "l"(p));
    return a;
}
__device__ __forceinline__ u32 lds32(u32 a) {
    u32 v; asm volatile("ld.shared.b32 %0, [%1];" : "=r"(v) : "r"(a)); return v;
}
__device__ __forceinline__ float ldsf(u32 a) {
    float v; asm volatile("ld.shared.f32 %0, [%1];" : "=f"(v) : "r"(a)); return v;
}
__device__ __forceinline__ void stsf(u32 a, float v) {
    asm volatile("st.shared.f32 [%0], %1;" :: "r"(a), "f"(v) : "memory");
}
__device__ __forceinline__ void sts32i(u32 a, int v) {
    asm volatile("st.shared.b32 [%0], %1;" :: "r"(a), "r"(v) : "memory");
}
__device__ __forceinline__ int lds32i(u32 a) {
    int v; asm volatile("ld.shared.b32 %0, [%1];" : "=r"(v) : "r"(a)); return v;
}
__device__ __forceinline__ void lds128(u32* r, u32 a) {
    asm volatile("ld.shared.v4.b32 {%0,%1,%2,%3}, [%4];"
                 : "=r"(r[0]), "=r"(r[1]), "=r"(r[2]), "=r"(r[3]) : "r"(a));
}
__device__ __forceinline__ void sts128(u32 a, u32 v0, u32 v1, u32 v2, u32 v3) {
    asm volatile("st.shared.v4.b32 [%0], {%1,%2,%3,%4};" :: "r"(a), "r"(v0), "r"(v1), "r"(v2), "r"(v3) : "memory");
}
__device__ __forceinline__ float silu_f(float x) { return x / (1.f + __expf(-x)); }

__device__ __forceinline__ u32 h2pack(float lo, float hi) {
    __half2 h = __floats2half2_rn(lo, hi);
    return *reinterpret_cast<u32*>(&h);
}

__device__ __forceinline__ void mma16816(float c[4], const u32* a, u32 b0, u32 b1) {
    asm("mma.sync.aligned.m16n8k16.row.col.f32.f16.f16.f32 "
        "{%0,%1,%2,%3}, {%4,%5,%6,%7}, {%8,%9}, {%0,%1,%2,%3};"
        : "+f"(c[0]), "+f"(c[1]), "+f"(c[2]), "+f"(c[3])
        : "r"(a[0]), "r"(a[1]), "r"(a[2]), "r"(a[3]), "r"(b0), "r"(b1));
}

#define SHFL(v, L) __shfl_sync(0xffffffffu, (v), (L))

// layer-2 chunk: single-pass hi (Ah*Bh), K=64, permuted v4 B loads
#define MMA_CHUNK(ch, C0, C1) do { \
    const u32 _rb = (u32)(((ch) * 8 + qr) * 144 + 32 * j); \
    u32 _rh[8]; \
    lds128(_rh,     BHI + _rb); lds128(_rh + 4, BHI + _rb + 16); \
    _Pragma("unroll") \
    for (int _kt = 0; _kt < 4; _kt++) { \
        mma16816(C0, ah + _kt * 4,      _rh[2 * _kt], _rh[2 * _kt + 1]); \
        mma16816(C1, ah + 16 + _kt * 4, _rh[2 * _kt], _rh[2 * _kt + 1]); \
    } \
} while (0)

// ---------------------------------------------------------------------------
// Kernel 1: per-node q pre-contraction, 2 threads per node (+ zero Z/out,
//           + reset edge tile counter for graph replay)
// ---------------------------------------------------------------------------
__global__ void q_kernel(const float* __restrict__ x,
                         const float* __restrict__ Wq0, const float* __restrict__ Wq1,
                         const float* __restrict__ Wd0, const float* __restrict__ Wd1,
                         float* __restrict__ out)
{
    int idx = blockIdx.x * blockDim.x + threadIdx.x;
    if (idx == 0) g_tile_ctr = 0u;
    int n = idx >> 1;
    int half = idx & 1;
    if (n >= N_NODES) return;
    float* o = out + (size_t)n * 20;
    float* qo = g_q + (size_t)n * 20;
    const float* xr = x + (size_t)n * 40;

    if (half == 0) {
        g_Z[n] = 0.f;
#pragma unroll
        for (int k = 0; k < 10; k++) o[k] = 0.f;
        float q0[8];
#pragma unroll
        for (int b = 0; b < 8; b++) {
            float acc = 0.f;
#pragma unroll
            for (int a = 0; a < 16; a++) acc = fmaf(xr[a], __ldg(Wq0 + a * 8 + b), acc);
            q0[b] = acc;
        }
#pragma unroll
        for (int b = 0; b < 8; b++) {
            float acc = 0.f;
#pragma unroll
            for (int a = 0; a < 8; a++) acc = fmaf(q0[a], __ldg(Wd0 + a * 8 + b), acc);
            qo[b] = acc * S0;
        }
    } else {
#pragma unroll
        for (int k = 10; k < 20; k++) o[k] = 0.f;
        float q1[12];
#pragma unroll
        for (int b = 0; b < 4; b++)
#pragma unroll
            for (int c = 0; c < 3; c++) {
                float acc = 0.f;
#pragma unroll
                for (int a = 0; a < 8; a++) acc = fmaf(xr[16 + a * 3 + c], __ldg(Wq1 + a * 4 + b), acc);
                q1[b * 3 + c] = acc;
            }
#pragma unroll
        for (int b = 0; b < 4; b++)
#pragma unroll
            for (int c = 0; c < 3; c++) {
                float acc = 0.f;
#pragma unroll
                for (int a = 0; a < 4; a++) acc = fmaf(q1[a * 3 + c], __ldg(Wd1 + a * 4 + b), acc);
                qo[8 + b * 3 + c] = acc * S1;
            }
    }
}

// ---------------------------------------------------------------------------
// Kernel 2: edge kernel — 512 threads, 2 tileslots, dynamic tile scheduler.
// ---------------------------------------------------------------------------
__global__ __launch_bounds__(512, 1)
void edge_kernel(const float* __restrict__ x, const int* __restrict__ ei,
                 const float* __restrict__ eattr, const float* __restrict__ emb,
                 const float* __restrict__ elen,
                 const float* __restrict__ Wk1, const float* __restrict__ Wk2,
                 const float* __restrict__ Wv1, const float* __restrict__ Wv2)
{
    extern __shared__ char smem[];
    const u32 sb = smem_u32(smem);
    const int tid = threadIdx.x;
    const int ts = tid >> 8;             // tileslot 0/1
    const int phase = (tid >> 7) & 1;    // 0 = K, 1 = V
    const int gt = tid & 127;            // edge row within tile
    const int lane = tid & 31;
    const int j = lane & 3;
    const int qr = lane >> 2;
    const int jh = j >> 1;
    const int wbase = (gt >> 5) << 5;
    const int barid = 1 + ts;

    // ---- stage W1 (fp16 hi only, [h-row][k=a], *0.25) ----
    for (int idx = tid; idx < 1024; idx += 512) {
        int a = idx >> 6, h = idx & 63;
        u32 off = (u32)(h * 32 + a * 2);
        *(u16*)(smem + OFF_W1KH + off) = __half_as_ushort(__float2half_rn(Wk1[idx] * 0.25f));
        *(u16*)(smem + OFF_W1VH + off) = __half_as_ushort(__float2half_rn(Wv1[idx] * 0.25f));
    }
    // ---- stage W2 (fp16 hi only, [n-row][k permuted], *0.125) ----
    for (int idx = tid; idx < 64 * 288; idx += 512) {
        int k = idx / 288, n = idx % 288;
        int p = k >> 1;
        int s = (p & 3) * 8 + (p >> 2);
        u32 off = (u32)(n * 144 + s * 4 + (k & 1) * 2);
        *(u16*)(smem + OFF_KHI + off) = __half_as_ushort(__float2half_rn(Wk2[idx] * 0.125f));
        *(u16*)(smem + OFF_VHI + off) = __half_as_ushort(__float2half_rn(Wv2[idx] * 0.125f));
    }
    __syncthreads();

    const u32 BHI = sb + (phase ? OFF_VHI : OFF_KHI);
    const u32 W1H = sb + (phase ? OFF_W1VH : OFF_W1KH);
    const u32 OPS = sb + (ts ? OFF_OPS1 : OFF_OPS0);
    const u32 EMB = sb + (ts ? OFF_EM1 : OFF_EM0);
    const u32 NEXT = sb + OFF_NEXT + (u32)(ts * 4);
    const int tbaseoff = (int)gridDim.x * 2;

    int lanev[4], rowv[4];
#pragma unroll
    for (int rr = 0; rr < 4; rr++) {
        lanev[rr] = (rr >> 1) * 16 + (rr & 1) * 8 + qr;
        rowv[rr] = wbase + lanev[rr];
    }

    int tile = blockIdx.x * 2 + ts;
    while (tile < NTILES) {
        const int tbase = tile * 128;
        const int e = tbase + gt;

        const int dst = ei[E_EDGES + e];
        const float4 ea = *(const float4*)(eattr + (size_t)e * 4);
        const float y0 = ea.x, y1a = ea.y, y1b = ea.z, y1c = ea.w;
        float el = 0.f;

        if (phase == 0) {
            // ---- K group: ops table (x gather) ----
            el = elen[e];
            const int src = ei[e];
            const float* xr = x + (size_t)src * 40;
            float xs_[16], xu_[24];
#pragma unroll
            for (int a = 0; a < 16; a++) xs_[a] = __ldg(xr + a);
#pragma unroll
            for (int a = 0; a < 24; a++) xu_[a] = __ldg(xr + 16 + a);
#pragma unroll
            for (int a = 0; a < 16; a++)
                stsf(OPS + (u32)((a * 128 + gt) * 4), xs_[a] * C_SU);      // su (ss = su*y0)
#pragma unroll
            for (int a = 0; a < 8; a++)
                stsf(OPS + (u32)(((16 + a) * 128 + gt) * 4),
                     (xu_[a * 3] * y1a + xu_[a * 3 + 1] * y1b + xu_[a * 3 + 2] * y1c) * C_UU);
            const float y0q = y0 * C_US;
#pragma unroll
            for (int a = 0; a < 24; a++)
                stsf(OPS + (u32)(((24 + a) * 128 + gt) * 4), xu_[a] * y0q);
        } else {
            // ---- V group: EM table (emb load + fp16 pack) ----
            const float4* ep = (const float4*)(emb + (size_t)e * 16);
            float em_[16];
#pragma unroll
            for (int k = 0; k < 4; k++) {
                float4 t = __ldg(ep + k);
                em_[4 * k] = t.x; em_[4 * k + 1] = t.y; em_[4 * k + 2] = t.z; em_[4 * k + 3] = t.w;
            }
            u32 hw[8];
#pragma unroll
            for (int w = 0; w < 8; w++) hw[w] = h2pack(em_[2 * w], em_[2 * w + 1]);
            const u32 rb = (u32)(gt * 32);
            sts128(EMB + rb,      hw[0], hw[1], hw[2], hw[3]);
            sts128(EMB + rb + 16, hw[4], hw[5], hw[6], hw[7]);
        }
        asm volatile("bar.sync %0, 256;" :: "r"(barid) : "memory");

        // ---- grab next tile for this slot (hidden under compute) ----
        if (phase == 0 && gt == 0) {
            u32 nn = atomicAdd(&g_tile_ctr, 1u);
            sts32i(NEXT, tbaseoff + (int)nn);
        }

        // ---- EM A-frags (hi only) ----
        u32 ehm[2][4];
#pragma unroll
        for (int mt = 0; mt < 2; mt++) {
            const u32 R0 = (u32)((wbase + 16 * mt + qr) * 32);
            ehm[mt][0] = lds32(EMB + R0 + 4 * j);
            ehm[mt][1] = lds32(EMB + R0 + 256 + 4 * j);
            ehm[mt][2] = lds32(EMB + R0 + 16 + 4 * j);
            ehm[mt][3] = lds32(EMB + R0 + 256 + 16 + 4 * j);
        }

        // ---- layer-1 via mma (K=16, single hi pass) ----
        u32 ah[32];
#pragma unroll
        for (int ktp = 0; ktp < 4; ktp++) {
            float cA0[4] = {0,0,0,0}, cA1[4] = {0,0,0,0};
            float cB0[4] = {0,0,0,0}, cB1[4] = {0,0,0,0};
            const u32 rA = (u32)(((2 * ktp) * 8 + qr) * 32 + 4 * j);
            const u32 rB = rA + 256;
            const u32 bh0A = lds32(W1H + rA), bh1A = lds32(W1H + rA + 16);
            const u32 bh0B = lds32(W1H + rB), bh1B = lds32(W1H + rB + 16);
            mma16816(cA0, ehm[0], bh0A, bh1A); mma16816(cA1, ehm[1], bh0A, bh1A);
            mma16816(cB0, ehm[0], bh0B, bh1B); mma16816(cB1, ehm[1], bh0B, bh1B);
            ah[ktp * 4 + 0]      = h2pack(silu_f(cA0[0]), silu_f(cA0[1]));
            ah[ktp * 4 + 1]      = h2pack(silu_f(cA0[2]), silu_f(cA0[3]));
            ah[ktp * 4 + 2]      = h2pack(silu_f(cB0[0]), silu_f(cB0[1]));
            ah[ktp * 4 + 3]      = h2pack(silu_f(cB0[2]), silu_f(cB0[3]));
            ah[16 + ktp * 4 + 0] = h2pack(silu_f(cA1[0]), silu_f(cA1[1]));
            ah[16 + ktp * 4 + 1] = h2pack(silu_f(cA1[2]), silu_f(cA1[3]));
            ah[16 + ktp * 4 + 2] = h2pack(silu_f(cB1[0]), silu_f(cB1[1]));
            ah[16 + ktp * 4 + 3] = h2pack(silu_f(cB1[2]), silu_f(cB1[3]));
        }

        float y0r[4];
#pragma unroll
        for (int rr = 0; rr < 4; rr++) y0r[rr] = SHFL(y0, lanev[rr]);

        // ---- layer-2: 36 n8 chunks, ops via SMEM ----
        float p0[4][2]  = {{0,0},{0,0},{0,0},{0,0}};
        float psu[4][2] = {{0,0},{0,0},{0,0},{0,0}};
        float pus[4][6] = {{0,0,0,0,0,0},{0,0,0,0,0,0},{0,0,0,0,0,0},{0,0,0,0,0,0}};

#pragma unroll
        for (int ch = 0; ch < 16; ch++) {          // ss: op = su_row(ch) * y0
            float A0[4] = {0,0,0,0}, B0[4] = {0,0,0,0};
            MMA_CHUNK(ch, A0, B0);
#pragma unroll
            for (int rr = 0; rr < 4; rr++) {
                float o = ldsf(OPS + (u32)((ch * 128 + rowv[rr]) * 4)) * y0r[rr];
                float c0 = (rr < 2) ? A0[(rr & 1) * 2]     : B0[(rr & 1) * 2];
                float c1 = (rr < 2) ? A0[(rr & 1) * 2 + 1] : B0[(rr & 1) * 2 + 1];
                p0[rr][0] = fmaf(c0, o, p0[rr][0]);
                p0[rr][1] = fmaf(c1, o, p0[rr][1]);
            }
        }
#pragma unroll
        for (int ch = 16; ch < 24; ch++) {         // uu: rows 16..23
            float A0[4] = {0,0,0,0}, B0[4] = {0,0,0,0};
            MMA_CHUNK(ch, A0, B0);
#pragma unroll
            for (int rr = 0; rr < 4; rr++) {
                float o = ldsf(OPS + (u32)((ch * 128 + rowv[rr]) * 4));
                float c0 = (rr < 2) ? A0[(rr & 1) * 2]     : B0[(rr & 1) * 2];
                float c1 = (rr < 2) ? A0[(rr & 1) * 2 + 1] : B0[(rr & 1) * 2 + 1];
                p0[rr][0] = fmaf(c0, o, p0[rr][0]);
                p0[rr][1] = fmaf(c1, o, p0[rr][1]);
            }
        }
#pragma unroll
        for (int ch = 24; ch < 32; ch++) {         // su: su_row(2*(ch-24)+jh), no y0
            float A0[4] = {0,0,0,0}, B0[4] = {0,0,0,0};
            MMA_CHUNK(ch, A0, B0);
            const int arow = 2 * (ch - 24) + jh;
#pragma unroll
            for (int rr = 0; rr < 4; rr++) {
                float o = ldsf(OPS + (u32)((arow * 128 + rowv[rr]) * 4));
                float c0 = (rr < 2) ? A0[(rr & 1) * 2]     : B0[(rr & 1) * 2];
                float c1 = (rr < 2) ? A0[(rr & 1) * 2 + 1] : B0[(rr & 1) * 2 + 1];
                psu[rr][0] = fmaf(c0, o, psu[rr][0]);
                psu[rr][1] = fmaf(c1, o, psu[rr][1]);
            }
        }
#pragma unroll
        for (int ch = 32; ch < 36; ch++) {         // us: rows 24 + 6*(ch-32) + 3*jh + c
            float A0[4] = {0,0,0,0}, B0[4] = {0,0,0,0};
            MMA_CHUNK(ch, A0, B0);
            const int arow = 24 + 6 * (ch - 32) + 3 * jh;
#pragma unroll
            for (int rr = 0; rr < 4; rr++) {
                const u32 ob = OPS + (u32)((arow * 128 + rowv[rr]) * 4);
                float o0 = ldsf(ob);
                float o1 = ldsf(ob + 512);
                float o2 = ldsf(ob + 1024);
                float c0 = (rr < 2) ? A0[(rr & 1) * 2]     : B0[(rr & 1) * 2];
                float c1 = (rr < 2) ? A0[(rr & 1) * 2 + 1] : B0[(rr & 1) * 2 + 1];
                pus[rr][0] = fmaf(c0, o0, pus[rr][0]);
                pus[rr][1] = fmaf(c0, o1, pus[rr][1]);
                pus[rr][2] = fmaf(c0, o2, pus[rr][2]);
                pus[rr][3] = fmaf(c1, o0, pus[rr][3]);
                pus[rr][4] = fmaf(c1, o1, pus[rr][4]);
                pus[rr][5] = fmaf(c1, o2, pus[rr][5]);
            }
        }

        // all OPS/EM reads for this tile done -> next tile's writers may proceed
        asm volatile("bar.sync %0, 256;" :: "r"(barid) : "memory");

        if (phase == 0) {
            // ---- logit finalize ----
#pragma unroll
            for (int rr = 0; rr < 4; rr++) {
                const int L = lanev[rr];
                const int edge = tbase + rowv[rr];
                const int dstr = SHFL(dst, L);
                const float ya = SHFL(y1a, L), yb = SHFL(y1b, L), yc = SHFL(y1c, L);
                const float elr = SHFL(el, L);
                const float* qd = g_q + (size_t)dstr * 20;
                const int b0 = (2 * j) & 3, b1 = (2 * j + 1) & 3;
                const float qa0 = __ldg(qd + 8 + 3 * b0), qa1 = __ldg(qd + 8 + 3 * b0 + 1), qa2 = __ldg(qd + 8 + 3 * b0 + 2);
                const float qb0 = __ldg(qd + 8 + 3 * b1), qb1 = __ldg(qd + 8 + 3 * b1 + 1), qb2 = __ldg(qd + 8 + 3 * b1 + 2);
                float dp = p0[rr][0] * __ldg(qd + 2 * j) + p0[rr][1] * __ldg(qd + 2 * j + 1);
                dp += psu[rr][0] * (ya * qa0 + yb * qa1 + yc * qa2);
                dp += psu[rr][1] * (ya * qb0 + yb * qb1 + yc * qb2);
                dp += pus[rr][0] * qa0 + pus[rr][1] * qa1 + pus[rr][2] * qa2;
                dp += pus[rr][3] * qb0 + pus[rr][4] * qb1 + pus[rr][5] * qb2;
                dp += __shfl_xor_sync(0xffffffffu, dp, 1);
                dp += __shfl_xor_sync(0xffffffffu, dp, 2);
                if (j == 0) {
                    const float t = 10.f * (1.f - elr * (1.f / 3.15f));
                    const float cut = (t > 0.f) ? expf(-1.f / fmaxf(t, 1e-6f)) : 0.f;
                    const float eat = cut * expf(dp);
                    g_e[edge] = eat;
                    atomicAdd(&g_Z[dstr], eat);
                }
            }
        } else {
            // ---- value finalize ----
#pragma unroll
            for (int rr = 0; rr < 4; rr++) {
                const int L = lanev[rr];
                const int edge = tbase + rowv[rr];
                const float ya = SHFL(y1a, L), yb = SHFL(y1b, L), yc = SHFL(y1c, L);
                float* vp = g_v + (size_t)edge * 20;
                vp[2 * j]     = p0[rr][0];
                vp[2 * j + 1] = p0[rr][1];
                const float s0v = psu[rr][0] + __shfl_xor_sync(0xffffffffu, psu[rr][0], 2);
                const float s1v = psu[rr][1] + __shfl_xor_sync(0xffffffffu, psu[rr][1], 2);
                float ux[6];
#pragma unroll
                for (int c = 0; c < 6; c++)
                    ux[c] = pus[rr][c] + __shfl_xor_sync(0xffffffffu, pus[rr][c], 2);
                if (j < 2) {
                    const int b0 = 2 * j, b1 = 2 * j + 1;
                    vp[8 + 3 * b0]     = fmaf(s0v, ya, ux[0]);
                    vp[8 + 3 * b0 + 1] = fmaf(s0v, yb, ux[1]);
                    vp[8 + 3 * b0 + 2] = fmaf(s0v, yc, ux[2]);
                    vp[8 + 3 * b1]     = fmaf(s1v, ya, ux[3]);
                    vp[8 + 3 * b1 + 1] = fmaf(s1v, yb, ux[4]);
                    vp[8 + 3 * b1 + 2] = fmaf(s1v, yc, ux[5]);
                }
            }
        }

        tile = lds32i(NEXT);   // published before bar#2 by this slot's leader
    }
}

// ---------------------------------------------------------------------------
// Kernel 3: normalize + scatter (vectorized red.global.add.v4.f32)
// ---------------------------------------------------------------------------
__global__ void scatter_kernel(const int* __restrict__ ei, float* __restrict__ out)
{
    int e = blockIdx.x * blockDim.x + threadIdx.x;
    if (e >= E_EDGES) return;
    int dst = ei[E_EDGES + e];
    float w = sqrtf(fmaxf(g_e[e] / g_Z[dst], 0.f));
    const float4* vp = (const float4*)(g_v + (size_t)e * 20);
    float* op = out + (size_t)dst * 20;
#pragma unroll
    for (int k4 = 0; k4 < 5; k4++) {
        float4 v = __ldg(vp + k4);
        asm volatile("red.global.add.v4.f32 [%0], {%1,%2,%3,%4};"
                     :: "l"(op + k4 * 4),
                        "f"(w * v.x), "f"(w * v.y), "f"(w * v.z), "f"(w * v.w)
                     : "memory");
    }
}

// ---------------------------------------------------------------------------
extern "C" void kernel_launch(void* const* d_in, const int* in_sizes, int n_in,
                              void* d_out, int out_size)
{
    const float* x    = (const float*)d_in[0];
    const int*   ei   = (const int*)d_in[1];
    const float* eatt = (const float*)d_in[2];
    const float* emb  = (const float*)d_in[3];
    const float* elen = (const float*)d_in[4];
    const float* Wq0  = (const float*)d_in[5];
    const float* Wq1  = (const float*)d_in[6];
    const float* Wk1  = (const float*)d_in[7];
    const float* Wk2  = (const float*)d_in[8];
    const float* Wv1  = (const float*)d_in[9];
    const float* Wv2  = (const float*)d_in[10];
    const float* Wd0  = (const float*)d_in[11];
    const float* Wd1  = (const float*)d_in[12];
    float* out = (float*)d_out;

    cudaFuncSetAttribute(edge_kernel, cudaFuncAttributeMaxDynamicSharedMemorySize, SMEM_BYTES);
    int dev = 0, nsm = 148;
    cudaGetDevice(&dev);
    cudaDeviceGetAttribute(&nsm, cudaDevAttrMultiProcessorCount, dev);

    q_kernel<<<(2 * N_NODES + 255) / 256, 256>>>(x, Wq0, Wq1, Wd0, Wd1, out);
    edge_kernel<<<nsm, 512, SMEM_BYTES>>>(x, ei, eatt, emb, elen, Wk1, Wk2, Wv1, Wv2);
    scatter_kernel<<<(E_EDGES + 255) / 256, 256>>>(ei, out);
    (void)in_sizes; (void)n_in; (void)out_size;
}